// round 16
// baseline (speedup 1.0000x reference)
#include <cuda_runtime.h>
#include <cuda_fp16.h>
#include <cstdint>

// Problem constants
#define BSZ   16
#define SEQ   12
#define NN    512
#define DIM   256
#define NH    8
#define NL    2
#define TOPK  16
#define DFF   1024
#define DH    32
#define NB    (BSZ*NN)        // 8192 sequences
#define ME    (NB*TOPK)       // 131072 encoder tokens

// ===================== helpers ==============================================
__device__ __forceinline__ uint32_t smem_to_u32(const void* p) {
    uint32_t a;
    asm("{ .reg .u64 t; cvta.to.shared.u64 t, %1; cvt.u32.u64 %0, t; }"
        : "=r"(a) : "l"(p));
    return a;
}
__device__ __forceinline__ void cpa16(uint32_t saddr, const void* g) {
    asm volatile("cp.async.cg.shared.global [%0], [%1], 16;\n" :: "r"(saddr), "l"(g));
}
#define CPA_COMMIT()  asm volatile("cp.async.commit_group;\n" ::: "memory")
#define CPA_WAIT1()   asm volatile("cp.async.wait_group 1;\n" ::: "memory")
#define CPA_WAIT0()   asm volatile("cp.async.wait_group 0;\n" ::: "memory")

__device__ __forceinline__ void ldm4(uint32_t* r, uint32_t a) {
    asm volatile("ldmatrix.sync.aligned.m8n8.x4.shared.b16 {%0,%1,%2,%3}, [%4];"
        : "=r"(r[0]), "=r"(r[1]), "=r"(r[2]), "=r"(r[3]) : "r"(a));
}
__device__ __forceinline__ void mma16816(float* c, const uint32_t* a, const uint32_t* b) {
    asm volatile("mma.sync.aligned.m16n8k16.row.col.f32.f16.f16.f32 "
        "{%0,%1,%2,%3}, {%4,%5,%6,%7}, {%8,%9}, {%0,%1,%2,%3};"
        : "+f"(c[0]), "+f"(c[1]), "+f"(c[2]), "+f"(c[3])
        : "r"(a[0]), "r"(a[1]), "r"(a[2]), "r"(a[3]), "r"(b[0]), "r"(b[1]));
}
__device__ __forceinline__ uint32_t packh2(__half a, __half b) {
    __half2 p = __halves2half2(a, b);
    return *reinterpret_cast<uint32_t*>(&p);
}

// ===================== device scratch ========================================
__device__ __half g_src [ (size_t)ME*DIM ];     // encoder residual (fp16)
__device__ float  g_tgt [ (size_t)NB*DIM ];     // decoder residual (fp32)
__device__ int    g_topk[ NN*TOPK ];
__device__ float  g_wc  [ 2*65536 ];            // dec-self combined weights fp32

__device__ __half g_y   [ (size_t)ME*DIM ];
__device__ __half g_mem [ (size_t)ME*DIM ];
__device__ __half g_qkv [ (size_t)ME*768 ];
__device__ __half g_att [ (size_t)ME*DIM ];
__device__ __half g_ffn [ (size_t)ME*DFF ];
__device__ __half g_ty  [ (size_t)NB*DIM ];
__device__ __half g_U   [ (size_t)NB*2048 ];
__device__ __half g_WM  [ (size_t)NB*2048 ];
__device__ __half g_tf  [ (size_t)NB*DFF ];

// weight arena ([N,K] fp16 row-major)
#define OFF_EQKV  0
#define OFF_EO    393216
#define OFF_EF1   524288
#define OFF_EF2   1048576
#define OFF_DSC   1572864
#define OFF_DM    1703936
#define OFF_DN    2752512
#define OFF_DF1   3801088
#define OFF_DF2   4325376
#define W_TOTAL   4849664
__device__ __half g_wb[ W_TOTAL ];

// ===================== weight transpose -> fp16 ==============================
__device__ __forceinline__ void wconv_tile(
        const float* __restrict__ W, __half* __restrict__ Wo,
        int K, int N, int k0, int n0, int tid) {
    __shared__ float ts[32][33];
    int tx = tid & 31, ty = tid >> 5;
    #pragma unroll
    for (int i = 0; i < 32; i += 8)
        ts[ty + i][tx] = W[(size_t)(k0 + ty + i) * N + n0 + tx];
    __syncthreads();
    #pragma unroll
    for (int i = 0; i < 32; i += 8)
        Wo[(size_t)(n0 + ty + i) * K + k0 + tx] = __float2half_rn(ts[tx][ty + i]);
}

__global__ void __launch_bounds__(256) wconv_kernel(
        const float* __restrict__ W, __half* __restrict__ Wo, int K, int N) {
    wconv_tile(W, Wo, K, N, blockIdx.y*32, blockIdx.x*32, threadIdx.x);
}

struct WEnt { const float* src; __half* dst; int K; int N; int tile0; };
struct WTab { WEnt e[16]; int n; };
__global__ void __launch_bounds__(256) wconv_batch(WTab tab) {
    int b = blockIdx.x;
    int idx = 0;
    for (int i = 1; i < 16; ++i)
        if (i < tab.n && b >= tab.e[i].tile0) idx = i;
    WEnt E = tab.e[idx];
    int local = b - E.tile0;
    int ntx = E.N >> 5;
    int n0 = (local % ntx) * 32, k0 = (local / ntx) * 32;
    wconv_tile(E.src, E.dst, E.K, E.N, k0, n0, threadIdx.x);
}

// dec-self combined: Wc[k,n] = sum_j Wv[k,j] * Wo[j,n]
__global__ void __launch_bounds__(256) wprod_kernel(
        const float* __restrict__ Wv, const float* __restrict__ Wo,
        float* __restrict__ Wc) {
    __shared__ float row[256];
    int k = blockIdx.x, t = threadIdx.x;
    row[t] = Wv[k*256 + t];
    __syncthreads();
    float acc = 0.f;
    for (int j = 0; j < 256; ++j) acc += row[j] * Wo[j*256 + t];
    Wc[k*256 + t] = acc;
}

// cross score fold
__global__ void __launch_bounds__(256) mfold_kernel(
        const float* __restrict__ Wq, const float* __restrict__ Wk,
        __half* __restrict__ Mout) {
    int n = blockIdx.x;
    int h = n >> 8, j = n & 255;
    int t = threadIdx.x;
    __shared__ float wk[32];
    if (t < 32) wk[t] = Wk[j*256 + h*32 + t];
    __syncthreads();
    float acc = 0.f;
    #pragma unroll
    for (int e = 0; e < 32; ++e) acc += Wq[t*256 + h*32 + e] * wk[e];
    Mout[(size_t)n*256 + t] = __float2half_rn(acc * 0.17677669529663687f);
}

// cross output fold
__global__ void __launch_bounds__(256) nfold_kernel(
        const float* __restrict__ Wv, const float* __restrict__ Wo,
        __half* __restrict__ Nout) {
    int n = blockIdx.x;
    int t = threadIdx.x;
    __shared__ float col[256];
    col[t] = Wo[t*256 + n];
    __syncthreads();
    for (int kk = t; kk < 2048; kk += 256) {
        int h = kk >> 8, j = kk & 255;
        float acc = 0.f;
        #pragma unroll
        for (int e = 0; e < 32; ++e) acc += Wv[j*256 + h*32 + e] * col[h*32 + e];
        Nout[(size_t)n*2048 + kk] = __float2half_rn(acc);
    }
}

// ===================== generic mma.sync GEMM (NT threads) ====================
// MODE 1: Cr16 += AB   2: Ch = relu(AB)   3: Ch = AB   4: Cr32 += AB
#define ROWB 144
#define NT   512
#define NWRP (NT/32)
#define MW   4                   // warps along M (4x4 warp grid)

template<int BM>
__device__ __forceinline__ void load_tiles(
        uint32_t sb, int t, const __half* __restrict__ A,
        const __half* __restrict__ B, int m0, int n0, int K, int k0) {
    #pragma unroll
    for (int i = 0; i < BM*8/NT; ++i) {
        int u = t + i*NT;
        int row = u >> 3, ch = u & 7;
        cpa16(sb + (uint32_t)(row*ROWB + ch*16),
              A + (size_t)(m0 + row) * K + k0 + ch*8);
    }
    #pragma unroll
    for (int i = 0; i < 128*8/NT; ++i) {
        int u = t + i*NT;
        int row = u >> 3, ch = u & 7;
        cpa16(sb + (uint32_t)(BM*ROWB + row*ROWB + ch*16),
              B + (size_t)(n0 + row) * K + k0 + ch*8);
    }
}

template<int MODE, int BM>
__global__ void __launch_bounds__(NT, 2) gemm_tc(
        const __half* __restrict__ A, const __half* __restrict__ B,
        __half* __restrict__ Cr16, float* __restrict__ Cr32,
        __half* __restrict__ Ch, int M, int K, int N) {
    extern __shared__ char smem[];
    constexpr int I = BM / (MW * 16);       // 16-row m-frags per warp
    constexpr int STGB = (BM + 128) * ROWB;
    uint32_t sb = smem_to_u32(smem);
    int t = threadIdx.x, wid = t >> 5, lane = t & 31;
    int m0 = blockIdx.y * BM, n0 = blockIdx.x * 128;
    int wm = (wid & (MW-1)) * (BM / MW);
    int wn = (wid / MW) * 32;

    float acc[I][4][4];
    #pragma unroll
    for (int i = 0; i < I; ++i)
        #pragma unroll
        for (int j = 0; j < 4; ++j)
            #pragma unroll
            for (int e = 0; e < 4; ++e) acc[i][j][e] = 0.f;

    const int NC = K >> 6;
    load_tiles<BM>(sb, t, A, B, m0, n0, K, 0);
    CPA_COMMIT();

    for (int c = 0; c < NC; ++c) {
        if (c + 1 < NC) {
            load_tiles<BM>(sb + ((c + 1) & 1) * STGB, t, A, B, m0, n0, K, (c + 1) * 64);
            CPA_COMMIT();
            CPA_WAIT1();
        } else {
            CPA_WAIT0();
        }
        __syncthreads();
        uint32_t st = sb + (c & 1) * STGB;
        #pragma unroll
        for (int ks = 0; ks < 4; ++ks) {
            uint32_t bh[2][4];
            #pragma unroll
            for (int p = 0; p < 2; ++p) {
                uint32_t nrow = (uint32_t)(wn + p*16 + ((lane >> 4) & 1)*8 + (lane & 7));
                uint32_t boff = (uint32_t)(BM*ROWB) + nrow*ROWB + ks*32 + ((lane >> 3) & 1)*16;
                ldm4(bh[p], st + boff);
            }
            #pragma unroll
            for (int i = 0; i < I; ++i) {
                uint32_t arow = (uint32_t)(wm + i*16 + (lane & 15));
                uint32_t aoff = arow*ROWB + ks*32 + (lane >> 4)*16;
                uint32_t ah[4];
                ldm4(ah, st + aoff);
                #pragma unroll
                for (int j = 0; j < 4; ++j)
                    mma16816(acc[i][j], ah, &bh[j >> 1][(j & 1) * 2]);
            }
        }
        __syncthreads();
    }

    int qrow = lane >> 2, qcol = (lane & 3) * 2;
    #pragma unroll
    for (int i = 0; i < I; ++i) {
        #pragma unroll
        for (int half_ = 0; half_ < 2; ++half_) {
            int r = m0 + wm + i*16 + qrow + half_*8;
            size_t rowoff = (size_t)r * N;
            #pragma unroll
            for (int j = 0; j < 4; ++j) {
                int gc = n0 + wn + j*8 + qcol;
                float v0 = acc[i][j][half_*2 + 0];
                float v1 = acc[i][j][half_*2 + 1];
                if (MODE == 1) {
                    __half2 o = *reinterpret_cast<const __half2*>(Cr16 + rowoff + gc);
                    *reinterpret_cast<uint32_t*>(Cr16 + rowoff + gc) =
                        packh2(__float2half_rn(__half2float(o.x) + v0),
                               __float2half_rn(__half2float(o.y) + v1));
                } else if (MODE == 4) {
                    float2 o = *reinterpret_cast<const float2*>(Cr32 + rowoff + gc);
                    *reinterpret_cast<float2*>(Cr32 + rowoff + gc) =
                        make_float2(o.x + v0, o.y + v1);
                } else {
                    if (MODE == 2) { v0 = fmaxf(v0, 0.f); v1 = fmaxf(v1, 0.f); }
                    *reinterpret_cast<uint32_t*>(Ch + rowoff + gc) =
                        packh2(__float2half_rn(v0), __float2half_rn(v1));
                }
            }
        }
    }
}

// ===================== top-K (exact, stable) =================================
__global__ void __launch_bounds__(256) topk_kernel(const float* __restrict__ A,
                                                   int* __restrict__ topk) {
    __shared__ float vals[512];
    __shared__ float rv[256];
    __shared__ int   ri[256];
    int r = blockIdx.x, t = threadIdx.x;
    vals[t]       = A[(size_t)r*512 + t];
    vals[t + 256] = A[(size_t)r*512 + t + 256];
    __syncthreads();
    for (int it = 0; it < TOPK; ++it) {
        float bv = vals[t]; int bi = t;
        float v2 = vals[t + 256];
        if (v2 > bv) { bv = v2; bi = t + 256; }
        rv[t] = bv; ri[t] = bi;
        __syncthreads();
        for (int s = 128; s > 0; s >>= 1) {
            if (t < s) {
                float ov = rv[t + s]; int oi = ri[t + s];
                if (ov > rv[t] || (ov == rv[t] && oi < ri[t])) { rv[t] = ov; ri[t] = oi; }
            }
            __syncthreads();
        }
        if (t == 0) { topk[r*TOPK + it] = ri[0]; vals[ri[0]] = -3.402823466e38f; }
        __syncthreads();
    }
}

// ===================== embeddings ============================================
__device__ __forceinline__ float pe_val(int pos, int d) {
    int e = d & ~1;
    float div = __expf(-(float)e * (logf(10000.0f) / (float)DIM));
    float ang = (float)pos * div;
    return (d & 1) ? cosf(ang) : sinf(ang);
}
__global__ void __launch_bounds__(256) embed_src_kernel(
        const float* __restrict__ x_c, const float* __restrict__ Wsrc,
        const int* __restrict__ topk, __half* __restrict__ src) {
    __shared__ float xs[SEQ];
    int tok = blockIdx.x, t = threadIdx.x;
    int bn = tok / TOPK, kk = tok % TOPK;
    int b = bn / NN, n = bn % NN;
    int node = topk[n*TOPK + kk];
    if (t < SEQ) xs[t] = x_c[((size_t)b*SEQ + t)*NN + node];
    __syncthreads();
    float acc = 0.f;
    #pragma unroll
    for (int s = 0; s < SEQ; ++s) acc += xs[s] * Wsrc[s*DIM + t];
    src[(size_t)tok*DIM + t] = __float2half_rn(acc * 16.0f + pe_val(kk, t));
}
__global__ void __launch_bounds__(256) embed_tgt_kernel(
        const float* __restrict__ x_c, const float* __restrict__ Wtgt,
        float* __restrict__ tgt) {
    __shared__ float xs[SEQ];
    int bn = blockIdx.x, t = threadIdx.x;
    int b = bn / NN, n = bn % NN;
    if (t < SEQ) xs[t] = x_c[((size_t)b*SEQ + t)*NN + n];
    __syncthreads();
    float acc = 0.f;
    #pragma unroll
    for (int s = 0; s < SEQ; ++s) acc += xs[s] * Wtgt[s*DIM + t];
    float pe0 = (t & 1) ? 1.0f : 0.0f;
    tgt[(size_t)bn*DIM + t] = acc * 16.0f + pe0;
}

// ===================== layernorm (vectorized) ================================
__global__ void __launch_bounds__(256) ln_h2h_kernel(
        const __half* __restrict__ in, __half* __restrict__ oh) {
    int wid = threadIdx.x >> 5, lane = threadIdx.x & 31;
    size_t row = (size_t)blockIdx.x * 8 + wid;
    uint4 v = reinterpret_cast<const uint4*>(in + row*DIM)[lane];
    __half* hv = reinterpret_cast<__half*>(&v);
    float x[8];
    #pragma unroll
    for (int i = 0; i < 8; ++i) x[i] = __half2float(hv[i]);
    float s = 0.f;
    #pragma unroll
    for (int i = 0; i < 8; ++i) s += x[i];
    #pragma unroll
    for (int o = 16; o > 0; o >>= 1) s += __shfl_xor_sync(0xffffffffu, s, o);
    float m = s * (1.0f/DIM);
    float var = 0.f;
    #pragma unroll
    for (int i = 0; i < 8; ++i) { float d = x[i] - m; var += d*d; }
    #pragma unroll
    for (int o = 16; o > 0; o >>= 1) var += __shfl_xor_sync(0xffffffffu, var, o);
    float rs = rsqrtf(var * (1.0f/DIM) + 1e-6f);
    uint4 w;
    __half* hw = reinterpret_cast<__half*>(&w);
    #pragma unroll
    for (int i = 0; i < 8; ++i) hw[i] = __float2half_rn((x[i] - m) * rs);
    reinterpret_cast<uint4*>(oh + row*DIM)[lane] = w;
}

__global__ void __launch_bounds__(256) ln_f2h_kernel(
        const float* __restrict__ in, __half* __restrict__ oh) {
    int wid = threadIdx.x >> 5, lane = threadIdx.x & 31;
    size_t row = (size_t)blockIdx.x * 8 + wid;
    const float4* p = reinterpret_cast<const float4*>(in + row*DIM);
    float4 a = p[lane], b = p[lane + 32];
    float x[8] = {a.x, a.y, a.z, a.w, b.x, b.y, b.z, b.w};
    float s = 0.f;
    #pragma unroll
    for (int i = 0; i < 8; ++i) s += x[i];
    #pragma unroll
    for (int o = 16; o > 0; o >>= 1) s += __shfl_xor_sync(0xffffffffu, s, o);
    float m = s * (1.0f/DIM);
    float var = 0.f;
    #pragma unroll
    for (int i = 0; i < 8; ++i) { float d = x[i] - m; var += d*d; }
    #pragma unroll
    for (int o = 16; o > 0; o >>= 1) var += __shfl_xor_sync(0xffffffffu, var, o);
    float rs = rsqrtf(var * (1.0f/DIM) + 1e-6f);
    uint2 w0, w1;
    __half* h0 = reinterpret_cast<__half*>(&w0);
    __half* h1 = reinterpret_cast<__half*>(&w1);
    #pragma unroll
    for (int i = 0; i < 4; ++i) {
        h0[i] = __float2half_rn((x[i]     - m) * rs);
        h1[i] = __float2half_rn((x[4 + i] - m) * rs);
    }
    reinterpret_cast<uint2*>(oh + row*DIM)[lane]      = w0;
    reinterpret_cast<uint2*>(oh + row*DIM + 128)[lane] = w1;
}

// ===================== encoder self-attention (vectorized) ===================
__global__ void __launch_bounds__(256) enc_attn_kernel(
        const __half* __restrict__ QKV, __half* __restrict__ O) {
    __shared__ float qs[TOPK*DIM];
    __shared__ float ks[TOPK*DIM];
    __shared__ float vs[TOPK*DIM];
    int bn = blockIdx.x, t = threadIdx.x;
    size_t base = (size_t)bn * TOPK * 768;
    #pragma unroll
    for (int it = 0; it < 2; ++it) {
        int i = t*8 + it*2048;
        int row = i >> 8, c = i & 255;
        size_t ro = base + (size_t)row * 768;
        uint4 vq = *reinterpret_cast<const uint4*>(QKV + ro + c);
        uint4 vk = *reinterpret_cast<const uint4*>(QKV + ro + 256 + c);
        uint4 vv = *reinterpret_cast<const uint4*>(QKV + ro + 512 + c);
        const __half* hq = reinterpret_cast<const __half*>(&vq);
        const __half* hk = reinterpret_cast<const __half*>(&vk);
        const __half* hv = reinterpret_cast<const __half*>(&vv);
        #pragma unroll
        for (int j = 0; j < 8; ++j) {
            qs[i + j] = __half2float(hq[j]);
            ks[i + j] = __half2float(hk[j]);
            vs[i + j] = __half2float(hv[j]);
        }
    }
    __syncthreads();
    const float scale = 0.17677669529663687f;
    float sc[8];
    #pragma unroll
    for (int i = 0; i < 8; ++i) {
        int e = t + i*256;
        int h = e >> 8, qi = (e >> 4) & 15, kj = e & 15;
        const float* qp = &qs[qi*DIM + h*DH];
        const float* kp = &ks[kj*DIM + h*DH];
        float d = 0.f;
        #pragma unroll
        for (int x = 0; x < DH; ++x) d += qp[x]*kp[x];
        sc[i] = d * scale;
    }
    __syncthreads();
    float* S = qs;
    #pragma unroll
    for (int i = 0; i < 8; ++i) S[t + i*256] = sc[i];
    __syncthreads();
    if (t < 128) {
        float* row = &S[t*16];
        float mx = row[0];
        #pragma unroll
        for (int j = 1; j < 16; ++j) mx = fmaxf(mx, row[j]);
        float sum = 0.f;
        #pragma unroll
        for (int j = 0; j < 16; ++j) { float a = expf(row[j]-mx); row[j] = a; sum += a; }
        float inv = 1.0f / sum;
        #pragma unroll
        for (int j = 0; j < 16; ++j) row[j] *= inv;
    }
    __syncthreads();
    size_t obase = (size_t)bn * TOPK * DIM;
    #pragma unroll
    for (int it = 0; it < 8; ++it) {
        int i2 = t*2 + it*512;
        int qi = i2 >> 8, c = i2 & 255, h = c >> 5;
        const float* row = &S[(h*16 + qi)*16];
        float a0 = 0.f, a1 = 0.f;
        #pragma unroll
        for (int kj = 0; kj < 16; ++kj) {
            a0 += row[kj] * vs[kj*DIM + c];
            a1 += row[kj] * vs[kj*DIM + c + 1];
        }
        *reinterpret_cast<uint32_t*>(O + obase + i2) =
            packh2(__float2half_rn(a0), __float2half_rn(a1));
    }
}

// ===================== decoder cross-attention (folded, vectorized) ==========
__global__ void __launch_bounds__(256) cross2_kernel(
        const __half* __restrict__ U, const __half* __restrict__ Mem,
        __half* __restrict__ WM) {
    __shared__ float ms[TOPK*DIM];
    __shared__ float us[2048];
    __shared__ float S[NH*TOPK];
    int bn = blockIdx.x, t = threadIdx.x;
    size_t mb = (size_t)bn * TOPK * DIM;
    size_t ub = (size_t)bn * 2048;
    #pragma unroll
    for (int it = 0; it < 2; ++it) {
        int i = t*8 + it*2048;
        uint4 vm = *reinterpret_cast<const uint4*>(Mem + mb + i);
        const __half* hm = reinterpret_cast<const __half*>(&vm);
        #pragma unroll
        for (int j = 0; j < 8; ++j) ms[i + j] = __half2float(hm[j]);
    }
    {
        int i = t*8;
        uint4 vu = *reinterpret_cast<const uint4*>(U + ub + i);
        const __half* hu = reinterpret_cast<const __half*>(&vu);
        #pragma unroll
        for (int j = 0; j < 8; ++j) us[i + j] = __half2float(hu[j]);
    }
    __syncthreads();
    if (t < NH*TOPK) {
        int h = t >> 4, kj = t & 15;
        const float* up = &us[h*256];
        const float* mp = &ms[kj*256];
        float d = 0.f;
        #pragma unroll 8
        for (int c = 0; c < 256; ++c) d += up[c] * mp[c];
        S[t] = d;
    }
    __syncthreads();
    if (t < NH) {
        float* row = &S[t*16];
        float mx = row[0];
        #pragma unroll
        for (int j = 1; j < 16; ++j) mx = fmaxf(mx, row[j]);
        float sum = 0.f;
        #pragma unroll
        for (int j = 0; j < 16; ++j) { float a = expf(row[j]-mx); row[j] = a; sum += a; }
        float inv = 1.0f / sum;
        #pragma unroll
        for (int j = 0; j < 16; ++j) row[j] *= inv;
    }
    __syncthreads();
    #pragma unroll
    for (int it = 0; it < 4; ++it) {
        int i2 = t*2 + it*512;
        int h = i2 >> 8, c = i2 & 255;
        const float* a = &S[h*16];
        float a0 = 0.f, a1 = 0.f;
        #pragma unroll
        for (int kj = 0; kj < 16; ++kj) {
            a0 += a[kj] * ms[kj*256 + c];
            a1 += a[kj] * ms[kj*256 + c + 1];
        }
        *reinterpret_cast<uint32_t*>(WM + ub + i2) =
            packh2(__float2half_rn(a0), __float2half_rn(a1));
    }
}

// ===================== final LN + generator ==================================
__global__ void __launch_bounds__(256) gen_kernel(
        const float* __restrict__ tgt, const float* __restrict__ Wgen,
        float* __restrict__ out) {
    __shared__ float red[256];
    __shared__ float y[256];
    __shared__ float stat[2];
    int bn = blockIdx.x, t = threadIdx.x;
    float v = tgt[(size_t)bn*DIM + t];
    red[t] = v; __syncthreads();
    for (int s = 128; s > 0; s >>= 1) { if (t < s) red[t] += red[t + s]; __syncthreads(); }
    if (t == 0) stat[0] = red[0] * (1.0f/DIM);
    __syncthreads();
    float d = v - stat[0];
    red[t] = d*d; __syncthreads();
    for (int s = 128; s > 0; s >>= 1) { if (t < s) red[t] += red[t + s]; __syncthreads(); }
    if (t == 0) stat[1] = rsqrtf(red[0] * (1.0f/DIM) + 1e-6f);
    __syncthreads();
    y[t] = d * stat[1];
    __syncthreads();
    if (t < SEQ) {
        float acc = 0.f;
        for (int dd = 0; dd < DIM; ++dd) acc += y[dd] * Wgen[dd*SEQ + t];
        out[(size_t)bn*SEQ + t] = acc;
    }
}

// ===================== host orchestration ====================================
static inline dim3 gg(int M, int N, int BM) { return dim3(N/128, M/BM); }
static inline int smem_gen(int BM)  { return 2 * (BM + 128) * ROWB; }

extern "C" void kernel_launch(void* const* d_in, const int* in_sizes, int n_in,
                              void* d_out, int out_size) {
    (void)in_sizes; (void)n_in; (void)out_size;
    const float* x_c      = (const float*)d_in[0];
    const float* A        = (const float*)d_in[1];
    const float* Wsrc     = (const float*)d_in[2];
    const float* Wtgt     = (const float*)d_in[3];
    const float* enc_attn = (const float*)d_in[4];
    const float* enc_ffn1 = (const float*)d_in[5];
    const float* enc_ffn2 = (const float*)d_in[6];
    const float* dec_self = (const float*)d_in[7];
    const float* dec_cross= (const float*)d_in[8];
    const float* dec_ffn1 = (const float*)d_in[9];
    const float* dec_ffn2 = (const float*)d_in[10];
    const float* Wgen     = (const float*)d_in[11];
    float* out = (float*)d_out;

    float *tgt, *wc; int* topk;
    __half *src, *y, *mem, *qkv, *att, *ffn, *ty, *U, *WM, *tf, *wb;
    cudaGetSymbolAddress((void**)&src,  g_src);
    cudaGetSymbolAddress((void**)&tgt,  g_tgt);
    cudaGetSymbolAddress((void**)&wc,   g_wc);
    cudaGetSymbolAddress((void**)&topk, g_topk);
    cudaGetSymbolAddress((void**)&y,    g_y);
    cudaGetSymbolAddress((void**)&mem,  g_mem);
    cudaGetSymbolAddress((void**)&qkv,  g_qkv);
    cudaGetSymbolAddress((void**)&att,  g_att);
    cudaGetSymbolAddress((void**)&ffn,  g_ffn);
    cudaGetSymbolAddress((void**)&ty,   g_ty);
    cudaGetSymbolAddress((void**)&U,    g_U);
    cudaGetSymbolAddress((void**)&WM,   g_WM);
    cudaGetSymbolAddress((void**)&tf,   g_tf);
    cudaGetSymbolAddress((void**)&wb,   g_wb);

    cudaFuncSetAttribute(gemm_tc<3,128>, cudaFuncAttributeMaxDynamicSharedMemorySize, smem_gen(128));
    cudaFuncSetAttribute(gemm_tc<1,128>, cudaFuncAttributeMaxDynamicSharedMemorySize, smem_gen(128));
    cudaFuncSetAttribute(gemm_tc<2,128>, cudaFuncAttributeMaxDynamicSharedMemorySize, smem_gen(128));
    cudaFuncSetAttribute(gemm_tc<4,64>,  cudaFuncAttributeMaxDynamicSharedMemorySize, smem_gen(64));
    cudaFuncSetAttribute(gemm_tc<3,64>,  cudaFuncAttributeMaxDynamicSharedMemorySize, smem_gen(64));
    cudaFuncSetAttribute(gemm_tc<2,64>,  cudaFuncAttributeMaxDynamicSharedMemorySize, smem_gen(64));

    const size_t WSZ = (size_t)DIM*DIM;
    const size_t FSZ = (size_t)DIM*DFF;

    topk_kernel<<<NN, 256>>>(A, topk);
    embed_src_kernel<<<ME, 256>>>(x_c, Wsrc, topk, src);
    embed_tgt_kernel<<<NB, 256>>>(x_c, Wtgt, tgt);

    // batched weight conversion (all plain weights)
    {
        WTab tab{}; int tile = 0, n = 0;
        auto add = [&](const float* s, __half* d, int K, int N_) {
            tab.e[n] = { s, d, K, N_, tile };
            tile += (K/32) * (N_/32); ++n;
        };
        for (int l = 0; l < NL; ++l) {
            for (int s = 0; s < 3; ++s)
                add(enc_attn + ((size_t)l*4 + s)*WSZ,
                    wb + OFF_EQKV + (size_t)l*768*256 + (size_t)s*256*256, DIM, DIM);
            add(enc_attn + ((size_t)l*4 + 3)*WSZ, wb + OFF_EO + l*WSZ, DIM, DIM);
            add(enc_ffn1 + l*FSZ, wb + OFF_EF1 + l*FSZ, DIM, DFF);
            add(enc_ffn2 + l*FSZ, wb + OFF_EF2 + l*FSZ, DFF, DIM);
        }
        for (int l = 0; l < NL; ++l) {
            add(dec_ffn1 + l*FSZ, wb + OFF_DF1 + l*FSZ, DIM, DFF);
            add(dec_ffn2 + l*FSZ, wb + OFF_DF2 + l*FSZ, DFF, DIM);
        }
        tab.n = n;
        wconv_batch<<<tile, 256>>>(tab);
    }
    wprod_kernel<<<256, 256>>>(dec_self + 2*WSZ, dec_self + 3*WSZ, wc);

    // ---- encoder (BM=128, 512 threads) ----
    for (int l = 0; l < NL; ++l) {
        ln_h2h_kernel<<<ME/8, 256>>>(src, y);
        gemm_tc<3,128><<<gg(ME,768,128), NT, smem_gen(128)>>>(y,
            wb + OFF_EQKV + (size_t)l*768*256, nullptr, nullptr, qkv, ME, 256, 768);
        enc_attn_kernel<<<NB, 256>>>(qkv, att);
        gemm_tc<1,128><<<gg(ME,DIM,128), NT, smem_gen(128)>>>(att,
            wb + OFF_EO + l*WSZ, src, nullptr, nullptr, ME, 256, DIM);
        ln_h2h_kernel<<<ME/8, 256>>>(src, y);
        gemm_tc<2,128><<<gg(ME,DFF,128), NT, smem_gen(128)>>>(y,
            wb + OFF_EF1 + l*FSZ, nullptr, nullptr, ffn, ME, 256, DFF);
        gemm_tc<1,128><<<gg(ME,DIM,128), NT, smem_gen(128)>>>(ffn,
            wb + OFF_EF2 + l*FSZ, src, nullptr, nullptr, ME, DFF, DIM);
    }
    ln_h2h_kernel<<<ME/8, 256>>>(src, mem);

    // remaining decoder weight prep
    wprod_kernel<<<256, 256>>>(dec_self + 6*WSZ, dec_self + 7*WSZ, wc + WSZ);
    wconv_kernel<<<dim3(8,8), 256>>>(wc,       wb + OFF_DSC,       DIM, DIM);
    wconv_kernel<<<dim3(8,8), 256>>>(wc + WSZ, wb + OFF_DSC + WSZ, DIM, DIM);
    for (int l = 0; l < NL; ++l) {
        mfold_kernel<<<2048, 256>>>(dec_cross + ((size_t)l*4 + 0)*WSZ,
                                    dec_cross + ((size_t)l*4 + 1)*WSZ,
                                    wb + OFF_DM + (size_t)l*2048*256);
        nfold_kernel<<<256, 256>>>(dec_cross + ((size_t)l*4 + 2)*WSZ,
                                   dec_cross + ((size_t)l*4 + 3)*WSZ,
                                   wb + OFF_DN + (size_t)l*256*2048);
    }

    // ---- decoder (BM=64, 512 threads, fp32 residual) ----
    for (int l = 0; l < NL; ++l) {
        ln_f2h_kernel<<<NB/8, 256>>>(tgt, ty);
        gemm_tc<4,64><<<gg(NB,DIM,64), NT, smem_gen(64)>>>(ty,
            wb + OFF_DSC + l*WSZ, nullptr, tgt, nullptr, NB, 256, DIM);
        ln_f2h_kernel<<<NB/8, 256>>>(tgt, ty);
        gemm_tc<3,64><<<gg(NB,2048,64), NT, smem_gen(64)>>>(ty,
            wb + OFF_DM + (size_t)l*2048*256, nullptr, nullptr, U, NB, 256, 2048);
        cross2_kernel<<<NB, 256>>>(U, mem, WM);
        gemm_tc<4,64><<<gg(NB,DIM,64), NT, smem_gen(64)>>>(WM,
            wb + OFF_DN + (size_t)l*256*2048, nullptr, tgt, nullptr, NB, 2048, DIM);
        ln_f2h_kernel<<<NB/8, 256>>>(tgt, ty);
        gemm_tc<2,64><<<gg(NB,DFF,64), NT, smem_gen(64)>>>(ty,
            wb + OFF_DF1 + l*FSZ, nullptr, nullptr, tf, NB, 256, DFF);
        gemm_tc<4,64><<<gg(NB,DIM,64), NT, smem_gen(64)>>>(tf,
            wb + OFF_DF2 + l*FSZ, nullptr, tgt, nullptr, NB, DFF, DIM);
    }

    gen_kernel<<<NB, 256>>>(tgt, Wgen, out);
}

// round 17
// speedup vs baseline: 1.0328x; 1.0328x over previous
#include <cuda_runtime.h>
#include <cuda_fp16.h>
#include <cstdint>

// Problem constants
#define BSZ   16
#define SEQ   12
#define NN    512
#define DIM   256
#define NH    8
#define NL    2
#define TOPK  16
#define DFF   1024
#define DH    32
#define NB    (BSZ*NN)        // 8192 sequences
#define ME    (NB*TOPK)       // 131072 encoder tokens

// ===================== helpers ==============================================
__device__ __forceinline__ uint32_t smem_to_u32(const void* p) {
    uint32_t a;
    asm("{ .reg .u64 t; cvta.to.shared.u64 t, %1; cvt.u32.u64 %0, t; }"
        : "=r"(a) : "l"(p));
    return a;
}
__device__ __forceinline__ void cpa16(uint32_t saddr, const void* g) {
    asm volatile("cp.async.cg.shared.global [%0], [%1], 16;\n" :: "r"(saddr), "l"(g));
}
#define CPA_COMMIT()  asm volatile("cp.async.commit_group;\n" ::: "memory")
#define CPA_WAIT1()   asm volatile("cp.async.wait_group 1;\n" ::: "memory")
#define CPA_WAIT0()   asm volatile("cp.async.wait_group 0;\n" ::: "memory")

__device__ __forceinline__ void ldm4(uint32_t* r, uint32_t a) {
    asm volatile("ldmatrix.sync.aligned.m8n8.x4.shared.b16 {%0,%1,%2,%3}, [%4];"
        : "=r"(r[0]), "=r"(r[1]), "=r"(r[2]), "=r"(r[3]) : "r"(a));
}
__device__ __forceinline__ void mma16816(float* c, const uint32_t* a, const uint32_t* b) {
    asm volatile("mma.sync.aligned.m16n8k16.row.col.f32.f16.f16.f32 "
        "{%0,%1,%2,%3}, {%4,%5,%6,%7}, {%8,%9}, {%0,%1,%2,%3};"
        : "+f"(c[0]), "+f"(c[1]), "+f"(c[2]), "+f"(c[3])
        : "r"(a[0]), "r"(a[1]), "r"(a[2]), "r"(a[3]), "r"(b[0]), "r"(b[1]));
}
__device__ __forceinline__ uint32_t packh2(__half a, __half b) {
    __half2 p = __halves2half2(a, b);
    return *reinterpret_cast<uint32_t*>(&p);
}

// ===================== device scratch ========================================
__device__ __half g_src [ (size_t)ME*DIM ];     // encoder residual (fp16)
__device__ float  g_tgt [ (size_t)NB*DIM ];     // decoder residual (fp32)
__device__ int    g_topk[ NN*TOPK ];
__device__ float  g_wc  [ 2*65536 ];            // dec-self combined weights fp32

__device__ __half g_y   [ (size_t)ME*DIM ];
__device__ __half g_mem [ (size_t)ME*DIM ];
__device__ __half g_qkv [ (size_t)ME*768 ];
__device__ __half g_att [ (size_t)ME*DIM ];
__device__ __half g_ffn [ (size_t)ME*DFF ];
__device__ __half g_ty  [ (size_t)NB*DIM ];
__device__ __half g_U   [ (size_t)NB*2048 ];
__device__ __half g_WM  [ (size_t)NB*2048 ];
__device__ __half g_tf  [ (size_t)NB*DFF ];

// weight arena ([N,K] fp16 row-major)
#define OFF_EQKV  0
#define OFF_EO    393216
#define OFF_EF1   524288
#define OFF_EF2   1048576
#define OFF_DSC   1572864
#define OFF_DM    1703936
#define OFF_DN    2752512
#define OFF_DF1   3801088
#define OFF_DF2   4325376
#define W_TOTAL   4849664
__device__ __half g_wb[ W_TOTAL ];

// ===================== weight transpose -> fp16 ==============================
__device__ __forceinline__ void wconv_tile(
        const float* __restrict__ W, __half* __restrict__ Wo,
        int K, int N, int k0, int n0, int tid) {
    __shared__ float ts[32][33];
    int tx = tid & 31, ty = tid >> 5;
    #pragma unroll
    for (int i = 0; i < 32; i += 8)
        ts[ty + i][tx] = W[(size_t)(k0 + ty + i) * N + n0 + tx];
    __syncthreads();
    #pragma unroll
    for (int i = 0; i < 32; i += 8)
        Wo[(size_t)(n0 + ty + i) * K + k0 + tx] = __float2half_rn(ts[tx][ty + i]);
}

__global__ void __launch_bounds__(256) wconv_kernel(
        const float* __restrict__ W, __half* __restrict__ Wo, int K, int N) {
    wconv_tile(W, Wo, K, N, blockIdx.y*32, blockIdx.x*32, threadIdx.x);
}

struct WEnt { const float* src; __half* dst; int K; int N; int tile0; };
struct WTab { WEnt e[16]; int n; };
__global__ void __launch_bounds__(256) wconv_batch(WTab tab) {
    int b = blockIdx.x;
    int idx = 0;
    for (int i = 1; i < 16; ++i)
        if (i < tab.n && b >= tab.e[i].tile0) idx = i;
    WEnt E = tab.e[idx];
    int local = b - E.tile0;
    int ntx = E.N >> 5;
    int n0 = (local % ntx) * 32, k0 = (local / ntx) * 32;
    wconv_tile(E.src, E.dst, E.K, E.N, k0, n0, threadIdx.x);
}

// dec-self combined: Wc[k,n] = sum_j Wv[k,j] * Wo[j,n]
__global__ void __launch_bounds__(256) wprod_kernel(
        const float* __restrict__ Wv, const float* __restrict__ Wo,
        float* __restrict__ Wc) {
    __shared__ float row[256];
    int k = blockIdx.x, t = threadIdx.x;
    row[t] = Wv[k*256 + t];
    __syncthreads();
    float acc = 0.f;
    for (int j = 0; j < 256; ++j) acc += row[j] * Wo[j*256 + t];
    Wc[k*256 + t] = acc;
}

// cross score fold
__global__ void __launch_bounds__(256) mfold_kernel(
        const float* __restrict__ Wq, const float* __restrict__ Wk,
        __half* __restrict__ Mout) {
    int n = blockIdx.x;
    int h = n >> 8, j = n & 255;
    int t = threadIdx.x;
    __shared__ float wk[32];
    if (t < 32) wk[t] = Wk[j*256 + h*32 + t];
    __syncthreads();
    float acc = 0.f;
    #pragma unroll
    for (int e = 0; e < 32; ++e) acc += Wq[t*256 + h*32 + e] * wk[e];
    Mout[(size_t)n*256 + t] = __float2half_rn(acc * 0.17677669529663687f);
}

// cross output fold
__global__ void __launch_bounds__(256) nfold_kernel(
        const float* __restrict__ Wv, const float* __restrict__ Wo,
        __half* __restrict__ Nout) {
    int n = blockIdx.x;
    int t = threadIdx.x;
    __shared__ float col[256];
    col[t] = Wo[t*256 + n];
    __syncthreads();
    for (int kk = t; kk < 2048; kk += 256) {
        int h = kk >> 8, j = kk & 255;
        float acc = 0.f;
        #pragma unroll
        for (int e = 0; e < 32; ++e) acc += Wv[j*256 + h*32 + e] * col[h*32 + e];
        Nout[(size_t)n*2048 + kk] = __float2half_rn(acc);
    }
}

// ===================== generic mma.sync GEMM (256 thr, 1 sync/chunk) =========
// MODE 1: Cr16 += AB   2: Ch = relu(AB)   3: Ch = AB   4: Cr32 += AB
// BM=128: 3-stage pipeline, occ 2.  BM=64: 2-stage, occ 3.
#define ROWB 144

template<int BM>
__device__ __forceinline__ void load_tiles(
        uint32_t sb, int t, const __half* __restrict__ A,
        const __half* __restrict__ B, int m0, int n0, int K, int k0) {
    #pragma unroll
    for (int i = 0; i < BM*8/256; ++i) {
        int u = t + i*256;
        int row = u >> 3, ch = u & 7;
        cpa16(sb + (uint32_t)(row*ROWB + ch*16),
              A + (size_t)(m0 + row) * K + k0 + ch*8);
    }
    #pragma unroll
    for (int i = 0; i < 4; ++i) {
        int u = t + i*256;
        int row = u >> 3, ch = u & 7;
        cpa16(sb + (uint32_t)(BM*ROWB + row*ROWB + ch*16),
              B + (size_t)(n0 + row) * K + k0 + ch*8);
    }
}

template<int MODE, int BM>
__global__ void __launch_bounds__(256, (BM == 64 ? 3 : 2)) gemm_tc(
        const __half* __restrict__ A, const __half* __restrict__ B,
        __half* __restrict__ Cr16, float* __restrict__ Cr32,
        __half* __restrict__ Ch, int M, int K, int N) {
    extern __shared__ char smem[];
    constexpr int I = BM / 32;
    constexpr int STGB = (BM + 128) * ROWB;
    constexpr int STAGES = (BM == 128) ? 3 : 2;
    uint32_t sb = smem_to_u32(smem);
    int t = threadIdx.x, wid = t >> 5, lane = t & 31;
    int m0 = blockIdx.y * BM, n0 = blockIdx.x * 128;
    int wm = (wid & 1) * (BM / 2);
    int wn = (wid >> 1) * 32;

    float acc[I][4][4];
    #pragma unroll
    for (int i = 0; i < I; ++i)
        #pragma unroll
        for (int j = 0; j < 4; ++j)
            #pragma unroll
            for (int e = 0; e < 4; ++e) acc[i][j][e] = 0.f;

    const int NC = K >> 6;
    #pragma unroll
    for (int p = 0; p < STAGES - 1; ++p) {
        load_tiles<BM>(sb + p * STGB, t, A, B, m0, n0, K, p * 64);
        CPA_COMMIT();
    }

    int stage = 0;
    for (int c = 0; c < NC; ++c) {
        if (STAGES == 3 && c + 1 < NC) { CPA_WAIT1(); } else { CPA_WAIT0(); }
        __syncthreads();
        if (c + STAGES - 1 < NC) {
            int ls = stage + STAGES - 1; if (ls >= STAGES) ls -= STAGES;
            load_tiles<BM>(sb + ls * STGB, t, A, B, m0, n0, K, (c + STAGES - 1) * 64);
            CPA_COMMIT();
        }
        uint32_t st = sb + stage * STGB;
        #pragma unroll
        for (int ks = 0; ks < 4; ++ks) {
            uint32_t bh[2][4];
            #pragma unroll
            for (int p = 0; p < 2; ++p) {
                uint32_t nrow = (uint32_t)(wn + p*16 + ((lane >> 4) & 1)*8 + (lane & 7));
                uint32_t boff = (uint32_t)(BM*ROWB) + nrow*ROWB + ks*32 + ((lane >> 3) & 1)*16;
                ldm4(bh[p], st + boff);
            }
            #pragma unroll
            for (int i = 0; i < I; ++i) {
                uint32_t arow = (uint32_t)(wm + i*16 + (lane & 15));
                uint32_t aoff = arow*ROWB + ks*32 + (lane >> 4)*16;
                uint32_t ah[4];
                ldm4(ah, st + aoff);
                #pragma unroll
                for (int j = 0; j < 4; ++j)
                    mma16816(acc[i][j], ah, &bh[j >> 1][(j & 1) * 2]);
            }
        }
        if (++stage == STAGES) stage = 0;
    }

    int qrow = lane >> 2, qcol = (lane & 3) * 2;
    #pragma unroll
    for (int i = 0; i < I; ++i) {
        #pragma unroll
        for (int half_ = 0; half_ < 2; ++half_) {
            int r = m0 + wm + i*16 + qrow + half_*8;
            size_t rowoff = (size_t)r * N;
            #pragma unroll
            for (int j = 0; j < 4; ++j) {
                int gc = n0 + wn + j*8 + qcol;
                float v0 = acc[i][j][half_*2 + 0];
                float v1 = acc[i][j][half_*2 + 1];
                if (MODE == 1) {
                    __half2 o = *reinterpret_cast<const __half2*>(Cr16 + rowoff + gc);
                    *reinterpret_cast<uint32_t*>(Cr16 + rowoff + gc) =
                        packh2(__float2half_rn(__half2float(o.x) + v0),
                               __float2half_rn(__half2float(o.y) + v1));
                } else if (MODE == 4) {
                    float2 o = *reinterpret_cast<const float2*>(Cr32 + rowoff + gc);
                    *reinterpret_cast<float2*>(Cr32 + rowoff + gc) =
                        make_float2(o.x + v0, o.y + v1);
                } else {
                    if (MODE == 2) { v0 = fmaxf(v0, 0.f); v1 = fmaxf(v1, 0.f); }
                    *reinterpret_cast<uint32_t*>(Ch + rowoff + gc) =
                        packh2(__float2half_rn(v0), __float2half_rn(v1));
                }
            }
        }
    }
}

// ===================== top-K (exact, stable) =================================
__global__ void __launch_bounds__(256) topk_kernel(const float* __restrict__ A,
                                                   int* __restrict__ topk) {
    __shared__ float vals[512];
    __shared__ float rv[256];
    __shared__ int   ri[256];
    int r = blockIdx.x, t = threadIdx.x;
    vals[t]       = A[(size_t)r*512 + t];
    vals[t + 256] = A[(size_t)r*512 + t + 256];
    __syncthreads();
    for (int it = 0; it < TOPK; ++it) {
        float bv = vals[t]; int bi = t;
        float v2 = vals[t + 256];
        if (v2 > bv) { bv = v2; bi = t + 256; }
        rv[t] = bv; ri[t] = bi;
        __syncthreads();
        for (int s = 128; s > 0; s >>= 1) {
            if (t < s) {
                float ov = rv[t + s]; int oi = ri[t + s];
                if (ov > rv[t] || (ov == rv[t] && oi < ri[t])) { rv[t] = ov; ri[t] = oi; }
            }
            __syncthreads();
        }
        if (t == 0) { topk[r*TOPK + it] = ri[0]; vals[ri[0]] = -3.402823466e38f; }
        __syncthreads();
    }
}

// ===================== embeddings ============================================
__device__ __forceinline__ float pe_val(int pos, int d) {
    int e = d & ~1;
    float div = __expf(-(float)e * (logf(10000.0f) / (float)DIM));
    float ang = (float)pos * div;
    return (d & 1) ? cosf(ang) : sinf(ang);
}
__global__ void __launch_bounds__(256) embed_src_kernel(
        const float* __restrict__ x_c, const float* __restrict__ Wsrc,
        const int* __restrict__ topk, __half* __restrict__ src) {
    __shared__ float xs[SEQ];
    int tok = blockIdx.x, t = threadIdx.x;
    int bn = tok / TOPK, kk = tok % TOPK;
    int b = bn / NN, n = bn % NN;
    int node = topk[n*TOPK + kk];
    if (t < SEQ) xs[t] = x_c[((size_t)b*SEQ + t)*NN + node];
    __syncthreads();
    float acc = 0.f;
    #pragma unroll
    for (int s = 0; s < SEQ; ++s) acc += xs[s] * Wsrc[s*DIM + t];
    src[(size_t)tok*DIM + t] = __float2half_rn(acc * 16.0f + pe_val(kk, t));
}
__global__ void __launch_bounds__(256) embed_tgt_kernel(
        const float* __restrict__ x_c, const float* __restrict__ Wtgt,
        float* __restrict__ tgt) {
    __shared__ float xs[SEQ];
    int bn = blockIdx.x, t = threadIdx.x;
    int b = bn / NN, n = bn % NN;
    if (t < SEQ) xs[t] = x_c[((size_t)b*SEQ + t)*NN + n];
    __syncthreads();
    float acc = 0.f;
    #pragma unroll
    for (int s = 0; s < SEQ; ++s) acc += xs[s] * Wtgt[s*DIM + t];
    float pe0 = (t & 1) ? 1.0f : 0.0f;
    tgt[(size_t)bn*DIM + t] = acc * 16.0f + pe0;
}

// ===================== layernorm (vectorized) ================================
__global__ void __launch_bounds__(256) ln_h2h_kernel(
        const __half* __restrict__ in, __half* __restrict__ oh) {
    int wid = threadIdx.x >> 5, lane = threadIdx.x & 31;
    size_t row = (size_t)blockIdx.x * 8 + wid;
    uint4 v = reinterpret_cast<const uint4*>(in + row*DIM)[lane];
    __half* hv = reinterpret_cast<__half*>(&v);
    float x[8];
    #pragma unroll
    for (int i = 0; i < 8; ++i) x[i] = __half2float(hv[i]);
    float s = 0.f;
    #pragma unroll
    for (int i = 0; i < 8; ++i) s += x[i];
    #pragma unroll
    for (int o = 16; o > 0; o >>= 1) s += __shfl_xor_sync(0xffffffffu, s, o);
    float m = s * (1.0f/DIM);
    float var = 0.f;
    #pragma unroll
    for (int i = 0; i < 8; ++i) { float d = x[i] - m; var += d*d; }
    #pragma unroll
    for (int o = 16; o > 0; o >>= 1) var += __shfl_xor_sync(0xffffffffu, var, o);
    float rs = rsqrtf(var * (1.0f/DIM) + 1e-6f);
    uint4 w;
    __half* hw = reinterpret_cast<__half*>(&w);
    #pragma unroll
    for (int i = 0; i < 8; ++i) hw[i] = __float2half_rn((x[i] - m) * rs);
    reinterpret_cast<uint4*>(oh + row*DIM)[lane] = w;
}

__global__ void __launch_bounds__(256) ln_f2h_kernel(
        const float* __restrict__ in, __half* __restrict__ oh) {
    int wid = threadIdx.x >> 5, lane = threadIdx.x & 31;
    size_t row = (size_t)blockIdx.x * 8 + wid;
    const float4* p = reinterpret_cast<const float4*>(in + row*DIM);
    float4 a = p[lane], b = p[lane + 32];
    float x[8] = {a.x, a.y, a.z, a.w, b.x, b.y, b.z, b.w};
    float s = 0.f;
    #pragma unroll
    for (int i = 0; i < 8; ++i) s += x[i];
    #pragma unroll
    for (int o = 16; o > 0; o >>= 1) s += __shfl_xor_sync(0xffffffffu, s, o);
    float m = s * (1.0f/DIM);
    float var = 0.f;
    #pragma unroll
    for (int i = 0; i < 8; ++i) { float d = x[i] - m; var += d*d; }
    #pragma unroll
    for (int o = 16; o > 0; o >>= 1) var += __shfl_xor_sync(0xffffffffu, var, o);
    float rs = rsqrtf(var * (1.0f/DIM) + 1e-6f);
    uint2 w0, w1;
    __half* h0 = reinterpret_cast<__half*>(&w0);
    __half* h1 = reinterpret_cast<__half*>(&w1);
    #pragma unroll
    for (int i = 0; i < 4; ++i) {
        h0[i] = __float2half_rn((x[i]     - m) * rs);
        h1[i] = __float2half_rn((x[4 + i] - m) * rs);
    }
    reinterpret_cast<uint2*>(oh + row*DIM)[lane]      = w0;
    reinterpret_cast<uint2*>(oh + row*DIM + 128)[lane] = w1;
}

// ===================== encoder self-attention (vectorized) ===================
__global__ void __launch_bounds__(256) enc_attn_kernel(
        const __half* __restrict__ QKV, __half* __restrict__ O) {
    __shared__ float qs[TOPK*DIM];
    __shared__ float ks[TOPK*DIM];
    __shared__ float vs[TOPK*DIM];
    int bn = blockIdx.x, t = threadIdx.x;
    size_t base = (size_t)bn * TOPK * 768;
    #pragma unroll
    for (int it = 0; it < 2; ++it) {
        int i = t*8 + it*2048;
        int row = i >> 8, c = i & 255;
        size_t ro = base + (size_t)row * 768;
        uint4 vq = *reinterpret_cast<const uint4*>(QKV + ro + c);
        uint4 vk = *reinterpret_cast<const uint4*>(QKV + ro + 256 + c);
        uint4 vv = *reinterpret_cast<const uint4*>(QKV + ro + 512 + c);
        const __half* hq = reinterpret_cast<const __half*>(&vq);
        const __half* hk = reinterpret_cast<const __half*>(&vk);
        const __half* hv = reinterpret_cast<const __half*>(&vv);
        #pragma unroll
        for (int j = 0; j < 8; ++j) {
            qs[i + j] = __half2float(hq[j]);
            ks[i + j] = __half2float(hk[j]);
            vs[i + j] = __half2float(hv[j]);
        }
    }
    __syncthreads();
    const float scale = 0.17677669529663687f;
    float sc[8];
    #pragma unroll
    for (int i = 0; i < 8; ++i) {
        int e = t + i*256;
        int h = e >> 8, qi = (e >> 4) & 15, kj = e & 15;
        const float* qp = &qs[qi*DIM + h*DH];
        const float* kp = &ks[kj*DIM + h*DH];
        float d = 0.f;
        #pragma unroll
        for (int x = 0; x < DH; ++x) d += qp[x]*kp[x];
        sc[i] = d * scale;
    }
    __syncthreads();
    float* S = qs;
    #pragma unroll
    for (int i = 0; i < 8; ++i) S[t + i*256] = sc[i];
    __syncthreads();
    if (t < 128) {
        float* row = &S[t*16];
        float mx = row[0];
        #pragma unroll
        for (int j = 1; j < 16; ++j) mx = fmaxf(mx, row[j]);
        float sum = 0.f;
        #pragma unroll
        for (int j = 0; j < 16; ++j) { float a = expf(row[j]-mx); row[j] = a; sum += a; }
        float inv = 1.0f / sum;
        #pragma unroll
        for (int j = 0; j < 16; ++j) row[j] *= inv;
    }
    __syncthreads();
    size_t obase = (size_t)bn * TOPK * DIM;
    #pragma unroll
    for (int it = 0; it < 8; ++it) {
        int i2 = t*2 + it*512;
        int qi = i2 >> 8, c = i2 & 255, h = c >> 5;
        const float* row = &S[(h*16 + qi)*16];
        float a0 = 0.f, a1 = 0.f;
        #pragma unroll
        for (int kj = 0; kj < 16; ++kj) {
            a0 += row[kj] * vs[kj*DIM + c];
            a1 += row[kj] * vs[kj*DIM + c + 1];
        }
        *reinterpret_cast<uint32_t*>(O + obase + i2) =
            packh2(__float2half_rn(a0), __float2half_rn(a1));
    }
}

// ===================== decoder cross-attention (folded, vectorized) ==========
__global__ void __launch_bounds__(256) cross2_kernel(
        const __half* __restrict__ U, const __half* __restrict__ Mem,
        __half* __restrict__ WM) {
    __shared__ float ms[TOPK*DIM];
    __shared__ float us[2048];
    __shared__ float S[NH*TOPK];
    int bn = blockIdx.x, t = threadIdx.x;
    size_t mb = (size_t)bn * TOPK * DIM;
    size_t ub = (size_t)bn * 2048;
    #pragma unroll
    for (int it = 0; it < 2; ++it) {
        int i = t*8 + it*2048;
        uint4 vm = *reinterpret_cast<const uint4*>(Mem + mb + i);
        const __half* hm = reinterpret_cast<const __half*>(&vm);
        #pragma unroll
        for (int j = 0; j < 8; ++j) ms[i + j] = __half2float(hm[j]);
    }
    {
        int i = t*8;
        uint4 vu = *reinterpret_cast<const uint4*>(U + ub + i);
        const __half* hu = reinterpret_cast<const __half*>(&vu);
        #pragma unroll
        for (int j = 0; j < 8; ++j) us[i + j] = __half2float(hu[j]);
    }
    __syncthreads();
    if (t < NH*TOPK) {
        int h = t >> 4, kj = t & 15;
        const float* up = &us[h*256];
        const float* mp = &ms[kj*256];
        float d = 0.f;
        #pragma unroll 8
        for (int c = 0; c < 256; ++c) d += up[c] * mp[c];
        S[t] = d;
    }
    __syncthreads();
    if (t < NH) {
        float* row = &S[t*16];
        float mx = row[0];
        #pragma unroll
        for (int j = 1; j < 16; ++j) mx = fmaxf(mx, row[j]);
        float sum = 0.f;
        #pragma unroll
        for (int j = 0; j < 16; ++j) { float a = expf(row[j]-mx); row[j] = a; sum += a; }
        float inv = 1.0f / sum;
        #pragma unroll
        for (int j = 0; j < 16; ++j) row[j] *= inv;
    }
    __syncthreads();
    #pragma unroll
    for (int it = 0; it < 4; ++it) {
        int i2 = t*2 + it*512;
        int h = i2 >> 8, c = i2 & 255;
        const float* a = &S[h*16];
        float a0 = 0.f, a1 = 0.f;
        #pragma unroll
        for (int kj = 0; kj < 16; ++kj) {
            a0 += a[kj] * ms[kj*256 + c];
            a1 += a[kj] * ms[kj*256 + c + 1];
        }
        *reinterpret_cast<uint32_t*>(WM + ub + i2) =
            packh2(__float2half_rn(a0), __float2half_rn(a1));
    }
}

// ===================== final LN + generator ==================================
__global__ void __launch_bounds__(256) gen_kernel(
        const float* __restrict__ tgt, const float* __restrict__ Wgen,
        float* __restrict__ out) {
    __shared__ float red[256];
    __shared__ float y[256];
    __shared__ float stat[2];
    int bn = blockIdx.x, t = threadIdx.x;
    float v = tgt[(size_t)bn*DIM + t];
    red[t] = v; __syncthreads();
    for (int s = 128; s > 0; s >>= 1) { if (t < s) red[t] += red[t + s]; __syncthreads(); }
    if (t == 0) stat[0] = red[0] * (1.0f/DIM);
    __syncthreads();
    float d = v - stat[0];
    red[t] = d*d; __syncthreads();
    for (int s = 128; s > 0; s >>= 1) { if (t < s) red[t] += red[t + s]; __syncthreads(); }
    if (t == 0) stat[1] = rsqrtf(red[0] * (1.0f/DIM) + 1e-6f);
    __syncthreads();
    y[t] = d * stat[1];
    __syncthreads();
    if (t < SEQ) {
        float acc = 0.f;
        for (int dd = 0; dd < DIM; ++dd) acc += y[dd] * Wgen[dd*SEQ + t];
        out[(size_t)bn*SEQ + t] = acc;
    }
}

// ===================== host orchestration ====================================
static inline dim3 gg(int M, int N, int BM) { return dim3(N/128, M/BM); }
static inline int smem_gen(int BM) {
    return (BM == 128 ? 3 : 2) * (BM + 128) * ROWB;
}

extern "C" void kernel_launch(void* const* d_in, const int* in_sizes, int n_in,
                              void* d_out, int out_size) {
    (void)in_sizes; (void)n_in; (void)out_size;
    const float* x_c      = (const float*)d_in[0];
    const float* A        = (const float*)d_in[1];
    const float* Wsrc     = (const float*)d_in[2];
    const float* Wtgt     = (const float*)d_in[3];
    const float* enc_attn = (const float*)d_in[4];
    const float* enc_ffn1 = (const float*)d_in[5];
    const float* enc_ffn2 = (const float*)d_in[6];
    const float* dec_self = (const float*)d_in[7];
    const float* dec_cross= (const float*)d_in[8];
    const float* dec_ffn1 = (const float*)d_in[9];
    const float* dec_ffn2 = (const float*)d_in[10];
    const float* Wgen     = (const float*)d_in[11];
    float* out = (float*)d_out;

    float *tgt, *wc; int* topk;
    __half *src, *y, *mem, *qkv, *att, *ffn, *ty, *U, *WM, *tf, *wb;
    cudaGetSymbolAddress((void**)&src,  g_src);
    cudaGetSymbolAddress((void**)&tgt,  g_tgt);
    cudaGetSymbolAddress((void**)&wc,   g_wc);
    cudaGetSymbolAddress((void**)&topk, g_topk);
    cudaGetSymbolAddress((void**)&y,    g_y);
    cudaGetSymbolAddress((void**)&mem,  g_mem);
    cudaGetSymbolAddress((void**)&qkv,  g_qkv);
    cudaGetSymbolAddress((void**)&att,  g_att);
    cudaGetSymbolAddress((void**)&ffn,  g_ffn);
    cudaGetSymbolAddress((void**)&ty,   g_ty);
    cudaGetSymbolAddress((void**)&U,    g_U);
    cudaGetSymbolAddress((void**)&WM,   g_WM);
    cudaGetSymbolAddress((void**)&tf,   g_tf);
    cudaGetSymbolAddress((void**)&wb,   g_wb);

    cudaFuncSetAttribute(gemm_tc<3,128>, cudaFuncAttributeMaxDynamicSharedMemorySize, smem_gen(128));
    cudaFuncSetAttribute(gemm_tc<1,128>, cudaFuncAttributeMaxDynamicSharedMemorySize, smem_gen(128));
    cudaFuncSetAttribute(gemm_tc<2,128>, cudaFuncAttributeMaxDynamicSharedMemorySize, smem_gen(128));
    cudaFuncSetAttribute(gemm_tc<4,64>,  cudaFuncAttributeMaxDynamicSharedMemorySize, smem_gen(64));
    cudaFuncSetAttribute(gemm_tc<3,64>,  cudaFuncAttributeMaxDynamicSharedMemorySize, smem_gen(64));
    cudaFuncSetAttribute(gemm_tc<2,64>,  cudaFuncAttributeMaxDynamicSharedMemorySize, smem_gen(64));

    const size_t WSZ = (size_t)DIM*DIM;
    const size_t FSZ = (size_t)DIM*DFF;

    topk_kernel<<<NN, 256>>>(A, topk);
    embed_src_kernel<<<ME, 256>>>(x_c, Wsrc, topk, src);
    embed_tgt_kernel<<<NB, 256>>>(x_c, Wtgt, tgt);

    // batched weight conversion (all plain weights)
    {
        WTab tab{}; int tile = 0, n = 0;
        auto add = [&](const float* s, __half* d, int K, int N_) {
            tab.e[n] = { s, d, K, N_, tile };
            tile += (K/32) * (N_/32); ++n;
        };
        for (int l = 0; l < NL; ++l) {
            for (int s = 0; s < 3; ++s)
                add(enc_attn + ((size_t)l*4 + s)*WSZ,
                    wb + OFF_EQKV + (size_t)l*768*256 + (size_t)s*256*256, DIM, DIM);
            add(enc_attn + ((size_t)l*4 + 3)*WSZ, wb + OFF_EO + l*WSZ, DIM, DIM);
            add(enc_ffn1 + l*FSZ, wb + OFF_EF1 + l*FSZ, DIM, DFF);
            add(enc_ffn2 + l*FSZ, wb + OFF_EF2 + l*FSZ, DFF, DIM);
        }
        for (int l = 0; l < NL; ++l) {
            add(dec_ffn1 + l*FSZ, wb + OFF_DF1 + l*FSZ, DIM, DFF);
            add(dec_ffn2 + l*FSZ, wb + OFF_DF2 + l*FSZ, DFF, DIM);
        }
        tab.n = n;
        wconv_batch<<<tile, 256>>>(tab);
    }
    wprod_kernel<<<256, 256>>>(dec_self + 2*WSZ, dec_self + 3*WSZ, wc);

    // ---- encoder (BM=128, 3-stage) ----
    for (int l = 0; l < NL; ++l) {
        ln_h2h_kernel<<<ME/8, 256>>>(src, y);
        gemm_tc<3,128><<<gg(ME,768,128), 256, smem_gen(128)>>>(y,
            wb + OFF_EQKV + (size_t)l*768*256, nullptr, nullptr, qkv, ME, 256, 768);
        enc_attn_kernel<<<NB, 256>>>(qkv, att);
        gemm_tc<1,128><<<gg(ME,DIM,128), 256, smem_gen(128)>>>(att,
            wb + OFF_EO + l*WSZ, src, nullptr, nullptr, ME, 256, DIM);
        ln_h2h_kernel<<<ME/8, 256>>>(src, y);
        gemm_tc<2,128><<<gg(ME,DFF,128), 256, smem_gen(128)>>>(y,
            wb + OFF_EF1 + l*FSZ, nullptr, nullptr, ffn, ME, 256, DFF);
        gemm_tc<1,128><<<gg(ME,DIM,128), 256, smem_gen(128)>>>(ffn,
            wb + OFF_EF2 + l*FSZ, src, nullptr, nullptr, ME, DFF, DIM);
    }
    ln_h2h_kernel<<<ME/8, 256>>>(src, mem);

    // remaining decoder weight prep
    wprod_kernel<<<256, 256>>>(dec_self + 6*WSZ, dec_self + 7*WSZ, wc + WSZ);
    wconv_kernel<<<dim3(8,8), 256>>>(wc,       wb + OFF_DSC,       DIM, DIM);
    wconv_kernel<<<dim3(8,8), 256>>>(wc + WSZ, wb + OFF_DSC + WSZ, DIM, DIM);
    for (int l = 0; l < NL; ++l) {
        mfold_kernel<<<2048, 256>>>(dec_cross + ((size_t)l*4 + 0)*WSZ,
                                    dec_cross + ((size_t)l*4 + 1)*WSZ,
                                    wb + OFF_DM + (size_t)l*2048*256);
        nfold_kernel<<<256, 256>>>(dec_cross + ((size_t)l*4 + 2)*WSZ,
                                   dec_cross + ((size_t)l*4 + 3)*WSZ,
                                   wb + OFF_DN + (size_t)l*256*2048);
    }

    // ---- decoder (BM=64, 2-stage, fp32 residual) ----
    for (int l = 0; l < NL; ++l) {
        ln_f2h_kernel<<<NB/8, 256>>>(tgt, ty);
        gemm_tc<4,64><<<gg(NB,DIM,64), 256, smem_gen(64)>>>(ty,
            wb + OFF_DSC + l*WSZ, nullptr, tgt, nullptr, NB, 256, DIM);
        ln_f2h_kernel<<<NB/8, 256>>>(tgt, ty);
        gemm_tc<3,64><<<gg(NB,2048,64), 256, smem_gen(64)>>>(ty,
            wb + OFF_DM + (size_t)l*2048*256, nullptr, nullptr, U, NB, 256, 2048);
        cross2_kernel<<<NB, 256>>>(U, mem, WM);
        gemm_tc<4,64><<<gg(NB,DIM,64), 256, smem_gen(64)>>>(WM,
            wb + OFF_DN + (size_t)l*256*2048, nullptr, tgt, nullptr, NB, 2048, DIM);
        ln_f2h_kernel<<<NB/8, 256>>>(tgt, ty);
        gemm_tc<2,64><<<gg(NB,DFF,64), 256, smem_gen(64)>>>(ty,
            wb + OFF_DF1 + l*FSZ, nullptr, nullptr, tf, NB, 256, DFF);
        gemm_tc<4,64><<<gg(NB,DIM,64), 256, smem_gen(64)>>>(tf,
            wb + OFF_DF2 + l*FSZ, nullptr, tgt, nullptr, NB, DFF, DIM);
    }

    gen_kernel<<<NB, 256>>>(tgt, Wgen, out);
}